// round 7
// baseline (speedup 1.0000x reference)
#include <cuda_runtime.h>
#include <math.h>

// k1: split-K matvec partials (UNCHANGED from R6 — measured at 80% DRAM).
// k2: float4 reduce + tanh.
// k3: grid-stride hebb update with deep MLP (rebuilt).

#define N 4096
#define SPLITS 512             // row splits (split-K)
#define ROWS_PER (N / SPLITS)  // 8 rows per split
#define MV_THREADS 256
#define COL_BLOCKS (N / (MV_THREADS * 4))  // 4

// Deterministic split-K scratch (8 MB). No atomics -> bit-identical replays.
__device__ float g_partial[SPLITS * N];

// ---- L2 policy helpers ----
__device__ __forceinline__ unsigned long long policy_evict_first() {
    unsigned long long p;
    asm("createpolicy.fractional.L2::evict_first.b64 %0, 1.0;" : "=l"(p));
    return p;
}
__device__ __forceinline__ unsigned long long policy_evict_last() {
    unsigned long long p;
    asm("createpolicy.fractional.L2::evict_last.b64 %0, 1.0;" : "=l"(p));
    return p;
}
__device__ __forceinline__ float4 ld_hint(const float4* p, unsigned long long pol) {
    float4 v;
    asm volatile("ld.global.nc.L2::cache_hint.v4.f32 {%0,%1,%2,%3}, [%4], %5;"
                 : "=f"(v.x), "=f"(v.y), "=f"(v.z), "=f"(v.w)
                 : "l"(p), "l"(pol));
    return v;
}

// ---------------------------------------------------------------------------
// Kernel 1 (unchanged): partial matvec, 2048 CTAs.
// ---------------------------------------------------------------------------
__global__ void __launch_bounds__(MV_THREADS) k_matvec_partial(
    const float* __restrict__ yin,
    const float* __restrict__ w,
    const float* __restrict__ alpha,
    const float* __restrict__ hebb)
{
    const int j  = blockIdx.x * (MV_THREADS * 4) + threadIdx.x * 4;
    const int r0 = blockIdx.y * ROWS_PER;

    const unsigned long long pol_ef = policy_evict_first();
    const unsigned long long pol_el = policy_evict_last();

    const float4* __restrict__ wp = reinterpret_cast<const float4*>(w     + (size_t)r0 * N + j);
    const float4* __restrict__ ap = reinterpret_cast<const float4*>(alpha + (size_t)r0 * N + j);
    const float4* __restrict__ hp = reinterpret_cast<const float4*>(hebb  + (size_t)r0 * N + j);
    const int stride4 = N / 4;

    float4 acc = make_float4(0.f, 0.f, 0.f, 0.f);

    #pragma unroll
    for (int i = 0; i < ROWS_PER; ++i) {
        const float  y  = __ldg(&yin[r0 + i]);
        const float4 w4 = ld_hint(wp + (size_t)i * stride4, pol_ef);
        const float4 a4 = ld_hint(ap + (size_t)i * stride4, pol_ef);
        const float4 h4 = ld_hint(hp + (size_t)i * stride4, pol_el);
        acc.x = fmaf(y, fmaf(a4.x, h4.x, w4.x), acc.x);
        acc.y = fmaf(y, fmaf(a4.y, h4.y, w4.y), acc.y);
        acc.z = fmaf(y, fmaf(a4.z, h4.z, w4.z), acc.z);
        acc.w = fmaf(y, fmaf(a4.w, h4.w, w4.w), acc.w);
    }

    *reinterpret_cast<float4*>(&g_partial[(size_t)blockIdx.y * N + j]) = acc;
}

// ---------------------------------------------------------------------------
// Kernel 2: float4 reduce over SPLITS partials + tanh -> yout.
// 1024 float4 columns; 4 CTAs x 256 threads.
// ---------------------------------------------------------------------------
__global__ void __launch_bounds__(256) k_reduce_tanh(
    const float* __restrict__ input,
    float* __restrict__ out_yout)
{
    const int j4 = blockIdx.x * blockDim.x + threadIdx.x;   // float4 column
    if (j4 >= N / 4) return;

    const float4* __restrict__ gp = reinterpret_cast<const float4*>(g_partial) + j4;
    float4 s = make_float4(0.f, 0.f, 0.f, 0.f);
    #pragma unroll 16
    for (int p = 0; p < SPLITS; ++p) {
        const float4 v = gp[(size_t)p * (N / 4)];
        s.x += v.x; s.y += v.y; s.z += v.z; s.w += v.w;
    }
    const float4 in = __ldg(reinterpret_cast<const float4*>(input) + j4);
    float4 yo;
    yo.x = tanhf(s.x + in.x);
    yo.y = tanhf(s.y + in.y);
    yo.z = tanhf(s.z + in.z);
    yo.w = tanhf(s.w + in.w);
    reinterpret_cast<float4*>(out_yout)[j4] = yo;
}

// ---------------------------------------------------------------------------
// Kernel 3: grid-stride hebb update, 8 unrolled float4 iters per thread.
// hebb read with evict_first (demote the k1 pin; last consumer).
// ---------------------------------------------------------------------------
#define HB_CTAS   2048
#define HB_THREADS 256
#define HB_ITERS  ((N * N / 4) / (HB_CTAS * HB_THREADS))   // 8

__global__ void __launch_bounds__(HB_THREADS) k_hebb_update(
    const float* __restrict__ hebb,
    const float* __restrict__ yin,
    const float* __restrict__ yout,   // = d_out
    const float* __restrict__ eta,
    float* __restrict__ out_hebb)     // = d_out + N
{
    const unsigned long long pol_ef = policy_evict_first();

    const float e   = __ldg(eta);
    const float ome = 1.f - e;

    const size_t tstride = (size_t)HB_CTAS * HB_THREADS;           // float4 units
    size_t idx4 = (size_t)blockIdx.x * HB_THREADS + threadIdx.x;

    const float4* __restrict__ hb = reinterpret_cast<const float4*>(hebb);
    const float4* __restrict__ yo4 = reinterpret_cast<const float4*>(yout);
    float4* __restrict__ ob = reinterpret_cast<float4*>(out_hebb);

    #pragma unroll
    for (int k = 0; k < HB_ITERS; ++k, idx4 += tstride) {
        const int i  = (int)(idx4 >> 10);          // row: 1024 float4 per row
        const int j4 = (int)(idx4 & 1023);         // float4 col

        const float  yie = __ldg(&yin[i]) * e;     // warp-uniform
        const float4 h   = ld_hint(hb + idx4, pol_ef);
        const float4 yo  = __ldg(yo4 + j4);

        float4 r;
        r.x = fmaf(ome, h.x, yie * yo.x);
        r.y = fmaf(ome, h.y, yie * yo.y);
        r.z = fmaf(ome, h.z, yie * yo.z);
        r.w = fmaf(ome, h.w, yie * yo.w);

        ob[idx4] = r;                              // plain write-back store
    }
}

extern "C" void kernel_launch(void* const* d_in, const int* in_sizes, int n_in,
                              void* d_out, int out_size)
{
    const float* input = (const float*)d_in[0];
    const float* yin   = (const float*)d_in[1];
    const float* hebb  = (const float*)d_in[2];
    const float* w     = (const float*)d_in[3];
    const float* alpha = (const float*)d_in[4];
    const float* eta   = (const float*)d_in[5];

    float* out      = (float*)d_out;
    float* out_yout = out;
    float* out_hebb = out + N;

    dim3 g1(COL_BLOCKS, SPLITS);   // 4 x 512 = 2048 CTAs
    k_matvec_partial<<<g1, MV_THREADS>>>(yin, w, alpha, hebb);

    k_reduce_tanh<<<(N / 4 + 255) / 256, 256>>>(input, out_yout);

    k_hebb_update<<<HB_CTAS, HB_THREADS>>>(hebb, yin, out_yout, eta, out_hebb);
}

// round 8
// speedup vs baseline: 1.0201x; 1.0201x over previous
#include <cuda_runtime.h>
#include <math.h>

// Best-measured composition, all createpolicy/evict_last experiments removed
// (they consistently poisoned k3's write stream).
//   k1: split-K matvec, SPLITS=512 (2048 CTAs) — measured 32.4us @ 80% DRAM.
//   k2: float4 reduce + tanh.
//   k3: hebb update, CTA-contiguous, 4 float4 per thread, __ldg + __stcs.

#define N 4096
#define SPLITS 512             // row splits (split-K)
#define ROWS_PER (N / SPLITS)  // 8 rows per split
#define MV_THREADS 256
#define COL_BLOCKS (N / (MV_THREADS * 4))  // 4

// Deterministic split-K scratch (8 MB). No atomics -> bit-identical replays.
__device__ float g_partial[SPLITS * N];

// ---------------------------------------------------------------------------
// Kernel 1: partial matvec, 2048 CTAs, 8 fully-unrolled rows.
// w/alpha: __ldcs (evict-normal streaming), hebb: __ldg. No policy registers.
// ---------------------------------------------------------------------------
__global__ void __launch_bounds__(MV_THREADS) k_matvec_partial(
    const float* __restrict__ yin,
    const float* __restrict__ w,
    const float* __restrict__ alpha,
    const float* __restrict__ hebb)
{
    const int j  = blockIdx.x * (MV_THREADS * 4) + threadIdx.x * 4;
    const int r0 = blockIdx.y * ROWS_PER;

    const float4* __restrict__ wp = reinterpret_cast<const float4*>(w     + (size_t)r0 * N + j);
    const float4* __restrict__ ap = reinterpret_cast<const float4*>(alpha + (size_t)r0 * N + j);
    const float4* __restrict__ hp = reinterpret_cast<const float4*>(hebb  + (size_t)r0 * N + j);
    const int stride4 = N / 4;

    float4 acc = make_float4(0.f, 0.f, 0.f, 0.f);

    #pragma unroll
    for (int i = 0; i < ROWS_PER; ++i) {
        const float  y  = __ldg(&yin[r0 + i]);
        const float4 w4 = __ldcs(wp + (size_t)i * stride4);
        const float4 a4 = __ldcs(ap + (size_t)i * stride4);
        const float4 h4 = __ldg (hp + (size_t)i * stride4);
        acc.x = fmaf(y, fmaf(a4.x, h4.x, w4.x), acc.x);
        acc.y = fmaf(y, fmaf(a4.y, h4.y, w4.y), acc.y);
        acc.z = fmaf(y, fmaf(a4.z, h4.z, w4.z), acc.z);
        acc.w = fmaf(y, fmaf(a4.w, h4.w, w4.w), acc.w);
    }

    *reinterpret_cast<float4*>(&g_partial[(size_t)blockIdx.y * N + j]) = acc;
}

// ---------------------------------------------------------------------------
// Kernel 2: float4 reduce over SPLITS partials + tanh -> yout.
// ---------------------------------------------------------------------------
__global__ void __launch_bounds__(256) k_reduce_tanh(
    const float* __restrict__ input,
    float* __restrict__ out_yout)
{
    const int j4 = blockIdx.x * blockDim.x + threadIdx.x;   // float4 column
    if (j4 >= N / 4) return;

    const float4* __restrict__ gp = reinterpret_cast<const float4*>(g_partial) + j4;
    float4 s = make_float4(0.f, 0.f, 0.f, 0.f);
    #pragma unroll 16
    for (int p = 0; p < SPLITS; ++p) {
        const float4 v = gp[(size_t)p * (N / 4)];
        s.x += v.x; s.y += v.y; s.z += v.z; s.w += v.w;
    }
    const float4 in = __ldg(reinterpret_cast<const float4*>(input) + j4);
    float4 yo;
    yo.x = tanhf(s.x + in.x);
    yo.y = tanhf(s.y + in.y);
    yo.z = tanhf(s.z + in.z);
    yo.w = tanhf(s.w + in.w);
    reinterpret_cast<float4*>(out_yout)[j4] = yo;
}

// ---------------------------------------------------------------------------
// Kernel 3: hebb update. CTA-contiguous tiles: each CTA owns a contiguous
// run of 1024 float4 (16 KB); each thread does 4 float4 at stride blockDim.
// Same instruction mix as R2's best-measured k3 (__ldg + __stcs), more MLP.
// ---------------------------------------------------------------------------
#define HB_THREADS 256
#define HB_ITERS   4
#define HB_TILE    (HB_THREADS * HB_ITERS)          // 1024 float4 per CTA
#define HB_CTAS    ((N * N / 4) / HB_TILE)          // 4096 CTAs

__global__ void __launch_bounds__(HB_THREADS) k_hebb_update(
    const float* __restrict__ hebb,
    const float* __restrict__ yin,
    const float* __restrict__ yout,   // = d_out
    const float* __restrict__ eta,
    float* __restrict__ out_hebb)     // = d_out + N
{
    const float e   = __ldg(eta);
    const float ome = 1.f - e;

    // CTA tile = exactly one row of the matrix (1024 float4 = 4096 floats).
    const int i = blockIdx.x;                        // row index
    const float yie = __ldg(&yin[i]) * e;            // uniform across CTA

    const float4* __restrict__ hb  = reinterpret_cast<const float4*>(hebb) + (size_t)i * (N / 4);
    const float4* __restrict__ yo4 = reinterpret_cast<const float4*>(yout);
    float4* __restrict__ ob        = reinterpret_cast<float4*>(out_hebb) + (size_t)i * (N / 4);

    #pragma unroll
    for (int k = 0; k < HB_ITERS; ++k) {
        const int j4 = k * HB_THREADS + threadIdx.x; // float4 col within row
        const float4 h  = __ldg(hb + j4);
        const float4 yo = __ldg(yo4 + j4);
        float4 r;
        r.x = fmaf(ome, h.x, yie * yo.x);
        r.y = fmaf(ome, h.y, yie * yo.y);
        r.z = fmaf(ome, h.z, yie * yo.z);
        r.w = fmaf(ome, h.w, yie * yo.w);
        __stcs(ob + j4, r);
    }
}

extern "C" void kernel_launch(void* const* d_in, const int* in_sizes, int n_in,
                              void* d_out, int out_size)
{
    const float* input = (const float*)d_in[0];
    const float* yin   = (const float*)d_in[1];
    const float* hebb  = (const float*)d_in[2];
    const float* w     = (const float*)d_in[3];
    const float* alpha = (const float*)d_in[4];
    const float* eta   = (const float*)d_in[5];

    float* out      = (float*)d_out;
    float* out_yout = out;
    float* out_hebb = out + N;

    dim3 g1(COL_BLOCKS, SPLITS);   // 4 x 512 = 2048 CTAs
    k_matvec_partial<<<g1, MV_THREADS>>>(yin, w, alpha, hebb);

    k_reduce_tanh<<<(N / 4 + 255) / 256, 256>>>(input, out_yout);

    k_hebb_update<<<HB_CTAS, HB_THREADS>>>(hebb, yin, out_yout, eta, out_hebb);
}

// round 9
// speedup vs baseline: 1.4869x; 1.4575x over previous
#include <cuda_runtime.h>
#include <math.h>

// Composition of the fastest measured variant of each phase:
//   k1 : split-K matvec, SPLITS=512, __ldcs(w,alpha)/__ldg(hebb) (32.4us ncu)
//   k2a: partial reduce 512 -> 4 per column (wide, coalesced)
//   k2b: final 4-way sum + tanh -> yout
//   k3 : flat hebb update, 16384 CTAs, 1 float4/thread, __ldg+__stcs
//        (byte-identical to R2's measured-fast version)

#define N 4096
#define SPLITS 512             // row splits (split-K)
#define ROWS_PER (N / SPLITS)  // 8 rows per split
#define MV_THREADS 256
#define COL_BLOCKS (N / (MV_THREADS * 4))  // 4

#define CHUNKS 4                       // stage-2 reduction fan-in
#define P_PER_CHUNK (SPLITS / CHUNKS)  // 128 partials per chunk

// Deterministic split-K scratch. No atomics -> bit-identical replays.
__device__ float g_partial[SPLITS * N];   // 8 MB
__device__ float g_partial2[CHUNKS * N];  // 64 KB

// ---------------------------------------------------------------------------
// Kernel 1: partial matvec, 2048 CTAs, 8 fully-unrolled rows.
// ---------------------------------------------------------------------------
__global__ void __launch_bounds__(MV_THREADS) k_matvec_partial(
    const float* __restrict__ yin,
    const float* __restrict__ w,
    const float* __restrict__ alpha,
    const float* __restrict__ hebb)
{
    const int j  = blockIdx.x * (MV_THREADS * 4) + threadIdx.x * 4;
    const int r0 = blockIdx.y * ROWS_PER;

    const float4* __restrict__ wp = reinterpret_cast<const float4*>(w     + (size_t)r0 * N + j);
    const float4* __restrict__ ap = reinterpret_cast<const float4*>(alpha + (size_t)r0 * N + j);
    const float4* __restrict__ hp = reinterpret_cast<const float4*>(hebb  + (size_t)r0 * N + j);
    const int stride4 = N / 4;

    float4 acc = make_float4(0.f, 0.f, 0.f, 0.f);

    #pragma unroll
    for (int i = 0; i < ROWS_PER; ++i) {
        const float  y  = __ldg(&yin[r0 + i]);
        const float4 w4 = __ldcs(wp + (size_t)i * stride4);
        const float4 a4 = __ldcs(ap + (size_t)i * stride4);
        const float4 h4 = __ldg (hp + (size_t)i * stride4);
        acc.x = fmaf(y, fmaf(a4.x, h4.x, w4.x), acc.x);
        acc.y = fmaf(y, fmaf(a4.y, h4.y, w4.y), acc.y);
        acc.z = fmaf(y, fmaf(a4.z, h4.z, w4.z), acc.z);
        acc.w = fmaf(y, fmaf(a4.w, h4.w, w4.w), acc.w);
    }

    *reinterpret_cast<float4*>(&g_partial[(size_t)blockIdx.y * N + j]) = acc;
}

// ---------------------------------------------------------------------------
// Kernel 2a: reduce 512 partials -> 4 per column. grid (16, 4) x 256 threads
// = 16384 threads; every load fully coalesced; 128 loads/thread, unroll 16.
// ---------------------------------------------------------------------------
__global__ void __launch_bounds__(256) k_reduce_stage1()
{
    const int j = blockIdx.x * 256 + threadIdx.x;   // column
    const int c = blockIdx.y;                        // chunk
    const float* __restrict__ gp = g_partial + (size_t)c * P_PER_CHUNK * N + j;

    float s = 0.f;
    #pragma unroll 16
    for (int p = 0; p < P_PER_CHUNK; ++p)
        s += gp[(size_t)p * N];

    g_partial2[(size_t)c * N + j] = s;
}

// ---------------------------------------------------------------------------
// Kernel 2b: final 4-way sum + input + tanh -> yout (d_out[0:N]).
// ---------------------------------------------------------------------------
__global__ void __launch_bounds__(256) k_reduce_tanh(
    const float* __restrict__ input,
    float* __restrict__ out_yout)
{
    const int j = blockIdx.x * 256 + threadIdx.x;
    float s = g_partial2[j] + g_partial2[N + j]
            + g_partial2[2 * N + j] + g_partial2[3 * N + j];
    out_yout[j] = tanhf(s + input[j]);
}

// ---------------------------------------------------------------------------
// Kernel 3: flat hebb update — byte-identical to the measured-fast R2 k3.
// ---------------------------------------------------------------------------
__global__ void __launch_bounds__(256) k_hebb_update(
    const float* __restrict__ hebb,
    const float* __restrict__ yin,
    const float* __restrict__ yout,   // = d_out
    const float* __restrict__ eta,
    float* __restrict__ out_hebb)     // = d_out + N
{
    const size_t t   = (size_t)blockIdx.x * blockDim.x + threadIdx.x;
    const size_t idx = t * 4;                 // element index in N*N
    const int i = (int)(idx >> 12);           // row (N = 2^12)
    const int j = (int)(idx & (N - 1));       // col

    const float e   = eta[0];
    const float ome = 1.f - e;
    const float yie = yin[i] * e;             // warp-uniform broadcast

    const float4 h  = __ldg(reinterpret_cast<const float4*>(hebb + idx));
    const float4 yo = __ldg(reinterpret_cast<const float4*>(yout + j));

    float4 r;
    r.x = fmaf(ome, h.x, yie * yo.x);
    r.y = fmaf(ome, h.y, yie * yo.y);
    r.z = fmaf(ome, h.z, yie * yo.z);
    r.w = fmaf(ome, h.w, yie * yo.w);

    __stcs(reinterpret_cast<float4*>(out_hebb + idx), r);
}

extern "C" void kernel_launch(void* const* d_in, const int* in_sizes, int n_in,
                              void* d_out, int out_size)
{
    const float* input = (const float*)d_in[0];
    const float* yin   = (const float*)d_in[1];
    const float* hebb  = (const float*)d_in[2];
    const float* w     = (const float*)d_in[3];
    const float* alpha = (const float*)d_in[4];
    const float* eta   = (const float*)d_in[5];

    float* out      = (float*)d_out;
    float* out_yout = out;
    float* out_hebb = out + N;

    dim3 g1(COL_BLOCKS, SPLITS);   // 4 x 512 = 2048 CTAs
    k_matvec_partial<<<g1, MV_THREADS>>>(yin, w, alpha, hebb);

    dim3 g2a(N / 256, CHUNKS);     // 16 x 4
    k_reduce_stage1<<<g2a, 256>>>();

    k_reduce_tanh<<<N / 256, 256>>>(input, out_yout);

    const int hb_blocks = (N * N) / (4 * 256);   // 16384
    k_hebb_update<<<hb_blocks, 256>>>(hebb, yin, out_yout, eta, out_hebb);
}

// round 10
// speedup vs baseline: 1.5375x; 1.0341x over previous
#include <cuda_runtime.h>
#include <math.h>

// R9 (62.2us) with ONLY k2a widened: 64 -> 256 CTAs (CHUNKS 4 -> 16).
//   k1 : split-K matvec, SPLITS=512 (unchanged, ~33us @ 80% DRAM)
//   k2a: reduce 512 -> 16 partials per column, 256 CTAs
//   k2b: 16-way sum + input + tanh -> yout
//   k3 : flat hebb update, 16384 CTAs, 1 float4/thread (unchanged, 19.3us)

#define N 4096
#define SPLITS 512             // row splits (split-K)
#define ROWS_PER (N / SPLITS)  // 8 rows per split
#define MV_THREADS 256
#define COL_BLOCKS (N / (MV_THREADS * 4))  // 4

#define CHUNKS 16                      // stage-2 reduction fan-in
#define P_PER_CHUNK (SPLITS / CHUNKS)  // 32 partials per chunk

// Deterministic split-K scratch. No atomics -> bit-identical replays.
__device__ float g_partial[SPLITS * N];   // 8 MB
__device__ float g_partial2[CHUNKS * N];  // 256 KB

// ---------------------------------------------------------------------------
// Kernel 1: partial matvec, 2048 CTAs, 8 fully-unrolled rows. (unchanged)
// ---------------------------------------------------------------------------
__global__ void __launch_bounds__(MV_THREADS) k_matvec_partial(
    const float* __restrict__ yin,
    const float* __restrict__ w,
    const float* __restrict__ alpha,
    const float* __restrict__ hebb)
{
    const int j  = blockIdx.x * (MV_THREADS * 4) + threadIdx.x * 4;
    const int r0 = blockIdx.y * ROWS_PER;

    const float4* __restrict__ wp = reinterpret_cast<const float4*>(w     + (size_t)r0 * N + j);
    const float4* __restrict__ ap = reinterpret_cast<const float4*>(alpha + (size_t)r0 * N + j);
    const float4* __restrict__ hp = reinterpret_cast<const float4*>(hebb  + (size_t)r0 * N + j);
    const int stride4 = N / 4;

    float4 acc = make_float4(0.f, 0.f, 0.f, 0.f);

    #pragma unroll
    for (int i = 0; i < ROWS_PER; ++i) {
        const float  y  = __ldg(&yin[r0 + i]);
        const float4 w4 = __ldcs(wp + (size_t)i * stride4);
        const float4 a4 = __ldcs(ap + (size_t)i * stride4);
        const float4 h4 = __ldg (hp + (size_t)i * stride4);
        acc.x = fmaf(y, fmaf(a4.x, h4.x, w4.x), acc.x);
        acc.y = fmaf(y, fmaf(a4.y, h4.y, w4.y), acc.y);
        acc.z = fmaf(y, fmaf(a4.z, h4.z, w4.z), acc.z);
        acc.w = fmaf(y, fmaf(a4.w, h4.w, w4.w), acc.w);
    }

    *reinterpret_cast<float4*>(&g_partial[(size_t)blockIdx.y * N + j]) = acc;
}

// ---------------------------------------------------------------------------
// Kernel 2a: reduce 512 partials -> 16 per column. grid (16,16) = 256 CTAs,
// 32 coalesced strided loads per thread, unrolled for MLP.
// ---------------------------------------------------------------------------
__global__ void __launch_bounds__(256) k_reduce_stage1()
{
    const int j = blockIdx.x * 256 + threadIdx.x;   // column
    const int c = blockIdx.y;                        // chunk
    const float* __restrict__ gp = g_partial + (size_t)c * P_PER_CHUNK * N + j;

    float s = 0.f;
    #pragma unroll
    for (int p = 0; p < P_PER_CHUNK; ++p)
        s += gp[(size_t)p * N];

    g_partial2[(size_t)c * N + j] = s;
}

// ---------------------------------------------------------------------------
// Kernel 2b: final 16-way sum + input + tanh -> yout (d_out[0:N]).
// ---------------------------------------------------------------------------
__global__ void __launch_bounds__(256) k_reduce_tanh(
    const float* __restrict__ input,
    float* __restrict__ out_yout)
{
    const int j = blockIdx.x * 256 + threadIdx.x;
    float s = 0.f;
    #pragma unroll
    for (int c = 0; c < CHUNKS; ++c)
        s += g_partial2[(size_t)c * N + j];
    out_yout[j] = tanhf(s + input[j]);
}

// ---------------------------------------------------------------------------
// Kernel 3: flat hebb update (unchanged — measured 19.3us).
// ---------------------------------------------------------------------------
__global__ void __launch_bounds__(256) k_hebb_update(
    const float* __restrict__ hebb,
    const float* __restrict__ yin,
    const float* __restrict__ yout,   // = d_out
    const float* __restrict__ eta,
    float* __restrict__ out_hebb)     // = d_out + N
{
    const size_t t   = (size_t)blockIdx.x * blockDim.x + threadIdx.x;
    const size_t idx = t * 4;                 // element index in N*N
    const int i = (int)(idx >> 12);           // row (N = 2^12)
    const int j = (int)(idx & (N - 1));       // col

    const float e   = eta[0];
    const float ome = 1.f - e;
    const float yie = yin[i] * e;             // warp-uniform broadcast

    const float4 h  = __ldg(reinterpret_cast<const float4*>(hebb + idx));
    const float4 yo = __ldg(reinterpret_cast<const float4*>(yout + j));

    float4 r;
    r.x = fmaf(ome, h.x, yie * yo.x);
    r.y = fmaf(ome, h.y, yie * yo.y);
    r.z = fmaf(ome, h.z, yie * yo.z);
    r.w = fmaf(ome, h.w, yie * yo.w);

    __stcs(reinterpret_cast<float4*>(out_hebb + idx), r);
}

extern "C" void kernel_launch(void* const* d_in, const int* in_sizes, int n_in,
                              void* d_out, int out_size)
{
    const float* input = (const float*)d_in[0];
    const float* yin   = (const float*)d_in[1];
    const float* hebb  = (const float*)d_in[2];
    const float* w     = (const float*)d_in[3];
    const float* alpha = (const float*)d_in[4];
    const float* eta   = (const float*)d_in[5];

    float* out      = (float*)d_out;
    float* out_yout = out;
    float* out_hebb = out + N;

    dim3 g1(COL_BLOCKS, SPLITS);   // 4 x 512 = 2048 CTAs
    k_matvec_partial<<<g1, MV_THREADS>>>(yin, w, alpha, hebb);

    dim3 g2a(N / 256, CHUNKS);     // 16 x 16 = 256 CTAs
    k_reduce_stage1<<<g2a, 256>>>();

    k_reduce_tanh<<<N / 256, 256>>>(input, out_yout);

    const int hb_blocks = (N * N) / (4 * 256);   // 16384
    k_hebb_update<<<hb_blocks, 256>>>(hebb, yin, out_yout, eta, out_hebb);
}